// round 3
// baseline (speedup 1.0000x reference)
#include <cuda_runtime.h>
#include <cuda_bf16.h>
#include <cstdint>

// ---------------- problem constants ----------------
#define T_STEPS 256
#define BATCH   64
#define HID     4096
#define G4      16384        // 4*HID
#define NINP    64
#define KC      64           // K elements per chunk
#define CHUNKS  65           // 64 hidden chunks + 1 input chunk
#define XCHUNKS 64
#define TILES   128          // CTAs; 32 hidden units per CTA
#define NSTAGE  4
#define A_BYTES 16384        // x chunk: 64 batch x 64 k fp32(tf32), fragment-packed
#define B_BYTES 32768        // W chunk: 64 k x 128 gate rows fp32(tf32), fragment-packed
#define STAGE_BYTES (A_BYTES + B_BYTES)
#define SMEM_DYN (NSTAGE*STAGE_BYTES + 1024)

// ---------------- device scratch (no cudaMalloc allowed) ----------------
__device__ uint32_t g_wpack[(size_t)TILES * CHUNKS * 8192]; // 272MB, B-fragment packed tf32
__device__ float    g_bsum[G4];
__device__ uint32_t g_embpack[(size_t)T_STEPS * 4096];      // emb chunk per t, A-fragment tf32
__device__ uint32_t g_xpack[2][XCHUNKS * 4096];             // h double buffer, A-fragment tf32
__device__ float    g_c[BATCH * HID];                       // cell state fp32

// ---------------- helpers ----------------
#define DI __device__ __forceinline__

DI uint32_t smem_u32(const void* p) {
    uint32_t a;
    asm("{ .reg .u64 t; cvta.to.shared.u64 t, %1; cvt.u32.u64 %0, t; }" : "=r"(a) : "l"(p));
    return a;
}
DI void cpasync16(uint32_t dst, const void* src) {
    asm volatile("cp.async.cg.shared.global [%0], [%1], 16;" :: "r"(dst), "l"(src) : "memory");
}
DI void cp_commit() { asm volatile("cp.async.commit_group;" ::: "memory"); }
template <int N> DI void cp_wait() { asm volatile("cp.async.wait_group %0;" :: "n"(N) : "memory"); }

DI uint32_t f2tf32(float v) {
    uint32_t r;
    asm("cvt.rna.tf32.f32 %0, %1;" : "=r"(r) : "f"(v));
    return r;
}
// m16n8k8 tf32 MMA, fp32 accum
DI void mma_tf32(float* d, const uint32_t* a, const uint32_t* b) {
    asm volatile(
        "mma.sync.aligned.m16n8k8.row.col.f32.tf32.tf32.f32 "
        "{%0,%1,%2,%3}, {%4,%5,%6,%7}, {%8,%9}, {%0,%1,%2,%3};"
        : "+f"(d[0]), "+f"(d[1]), "+f"(d[2]), "+f"(d[3])
        : "r"(a[0]), "r"(a[1]), "r"(a[2]), "r"(a[3]), "r"(b[0]), "r"(b[1]));
}
DI float sigm(float x) { return 1.0f / (1.0f + __expf(-x)); }

// ---------------- pack kernel ----------------
// B-fragment layout per (tile, kc): 8192 u32 = [w(4)][ks(8)][nt(4)][lane(32)][r(2)]
// value(w,ks,nt,lane,r): k = ks*8 + (lane&3) + r*4 ; n = w*32 + nt*8 + (lane>>2)
// gate g = w ; hid = tile*32 + (n&31). src row = g*HID + hid.
__global__ void pack_kernel(const float* __restrict__ w_ih, const float* __restrict__ w_hh) {
    int blk  = blockIdx.x;             // tile*CHUNKS + kc
    int tile = blk / CHUNKS;
    int kc   = blk % CHUNKS;
    uint32_t* dst = g_wpack + (size_t)blk * 8192;
    #pragma unroll
    for (int j = 0; j < 32; j++) {
        int v    = threadIdx.x + j * 256;
        int r    = v & 1;
        int lane = (v >> 1) & 31;
        int nt   = (v >> 6) & 3;
        int ks   = (v >> 8) & 7;
        int w    = v >> 11;
        int k    = ks * 8 + (lane & 3) + r * 4;
        int hid  = tile * 32 + nt * 8 + (lane >> 2);
        size_t srow = (size_t)w * HID + hid;
        float val = (kc < 64) ? w_hh[srow * HID + (size_t)kc * KC + k]
                              : w_ih[srow * NINP + k];
        dst[v] = f2tf32(val);
    }
}

// ---------------- init: bias sum, embedding A-fragment pack, h0/c0 ----------------
// A-fragment layout per chunk: 4096 u32 = [ks(8)][mt(4)][lane(32)][r(4)]
// value(ks,mt,lane,r): b = mt*16 + (lane>>2) + (r&1)*8 ; k = ks*8 + (lane&3) + (r>>1)*4
__global__ void init_kernel(const int* __restrict__ tokens,
                            const float* __restrict__ emb_table,
                            const float* __restrict__ b_ih,
                            const float* __restrict__ b_hh) {
    int i = blockIdx.x * blockDim.x + threadIdx.x;
    if (i < T_STEPS * 4096) {
        int t = i >> 12;
        int v = i & 4095;
        int r = v & 3, lane = (v >> 2) & 31, mt = (v >> 7) & 3, ks = v >> 9;
        int b = mt * 16 + (lane >> 2) + (r & 1) * 8;
        int k = ks * 8 + (lane & 3) + (r >> 1) * 4;
        int tok = tokens[t * BATCH + b];
        g_embpack[i] = f2tf32(emb_table[tok * NINP + k]);
    }
    if (i < XCHUNKS * 4096) g_xpack[0][i] = 0u;
    if (i < BATCH * HID)    g_c[i] = 0.0f;
    if (i < G4)             g_bsum[i] = b_ih[i] + b_hh[i];
}

// ---------------- one recurrent step ----------------
// grid = 128 CTAs, 128 threads (4 warps). Warp w owns gate-rows [32w,32w+32) (= gate w).
// D^T[batch 64][gate rows 128] += x(tf32) * W(tf32)  via mma.sync m16n8k8.
__global__ void __launch_bounds__(128, 1)
step_kernel(int t, const int* __restrict__ seq_len, float* __restrict__ out) {
    extern __shared__ char smem_raw[];
    const int tid  = threadIdx.x;
    const int warp = tid >> 5;
    const int lane = tid & 31;
    const int tile = blockIdx.x;

    uint32_t sb_raw = smem_u32(smem_raw);
    uint32_t sb = (sb_raw + 1023u) & ~1023u;
    char* smem_al = smem_raw + (sb - sb_raw);

    const uint32_t* wB   = g_wpack + (size_t)tile * (CHUNKS * 8192);
    const uint32_t* xcur = g_xpack[t & 1];
    const uint32_t* embt = g_embpack + (size_t)t * 4096;

    auto load_stage = [&](int kc, int s) {
        uint32_t ab = sb + (uint32_t)s * STAGE_BYTES;
        const char* asrc = (kc < 64) ? (const char*)(xcur + (size_t)kc * 4096)
                                     : (const char*)embt;
        #pragma unroll
        for (int i = 0; i < 8; i++) {                 // A: 16KB linear
            int u = i * 128 + tid;
            cpasync16(ab + (uint32_t)u * 16, asrc + (size_t)u * 16);
        }
        uint32_t bb = ab + A_BYTES;
        const char* bsrc = (const char*)(wB + (size_t)kc * 8192);
        #pragma unroll
        for (int i = 0; i < 16; i++) {                // B: 32KB linear
            int u = i * 128 + tid;
            cpasync16(bb + (uint32_t)u * 16, bsrc + (size_t)u * 16);
        }
    };

    #pragma unroll
    for (int s = 0; s < NSTAGE - 1; s++) { load_stage(s, s); cp_commit(); }

    float acc[4][4][4];                               // [mt][nt][c]
    #pragma unroll
    for (int mt = 0; mt < 4; mt++)
        #pragma unroll
        for (int nt = 0; nt < 4; nt++)
            #pragma unroll
            for (int c = 0; c < 4; c++) acc[mt][nt][c] = 0.0f;

    for (int k = 0; k < CHUNKS; ++k) {
        cp_wait<NSTAGE - 2>();
        __syncthreads();
        if (k + NSTAGE - 1 < CHUNKS) load_stage(k + NSTAGE - 1, (k + NSTAGE - 1) % NSTAGE);
        cp_commit();

        int s = k % NSTAGE;
        const char* sA = smem_al + (size_t)s * STAGE_BYTES;
        const char* sB = sA + A_BYTES;

        #pragma unroll
        for (int ks = 0; ks < 8; ks++) {
            uint32_t af[4][4];
            #pragma unroll
            for (int mt = 0; mt < 4; mt++) {
                uint4 vv = *(const uint4*)(sA + ks * 2048 + mt * 512 + lane * 16);
                af[mt][0] = vv.x; af[mt][1] = vv.y; af[mt][2] = vv.z; af[mt][3] = vv.w;
            }
            uint32_t bf[4][2];
            #pragma unroll
            for (int nt = 0; nt < 4; nt++) {
                uint2 vv = *(const uint2*)(sB + ((warp * 8 + ks) * 4 + nt) * 256 + lane * 8);
                bf[nt][0] = vv.x; bf[nt][1] = vv.y;
            }
            #pragma unroll
            for (int mt = 0; mt < 4; mt++)
                #pragma unroll
                for (int nt = 0; nt < 4; nt++)
                    mma_tf32(acc[mt][nt], af[mt], bf[nt]);
        }
    }

    cp_wait<0>();
    __syncthreads();

    // ---- epilogue: C fragments -> smem [batch 64][gate rows 128] (stride 132) ----
    float* gsm = (float*)smem_al;
    #pragma unroll
    for (int mt = 0; mt < 4; mt++)
        #pragma unroll
        for (int nt = 0; nt < 4; nt++) {
            int b0 = mt * 16 + (lane >> 2);
            int n  = warp * 32 + nt * 8 + 2 * (lane & 3);
            *(float2*)&gsm[b0 * 132 + n]       = make_float2(acc[mt][nt][0], acc[mt][nt][1]);
            *(float2*)&gsm[(b0 + 8) * 132 + n] = make_float2(acc[mt][nt][2], acc[mt][nt][3]);
        }
    __syncthreads();

    // LSTM update; write h in A-fragment-packed order (coalesced), c update, out.
    const int kc_out = tile >> 1;
    uint32_t* xn = g_xpack[(t + 1) & 1];
    #pragma unroll 4
    for (int i = 0; i < 16; i++) {
        int e      = i * 128 + tid;         // 2048 = [ksl(4)][mt(4)][lane(32)][r(4)]
        int r      = e & 3;
        int lane_w = (e >> 2) & 31;
        int mt     = (e >> 7) & 3;
        int ksl    = e >> 9;
        int hidl   = ksl * 8 + (lane_w & 3) + (r >> 1) * 4;   // 0..31
        int b      = mt * 16 + (lane_w >> 2) + (r & 1) * 8;   // 0..63
        float gi = gsm[b * 132 +  0 + hidl] + g_bsum[0 * HID + tile * 32 + hidl];
        float gf = gsm[b * 132 + 32 + hidl] + g_bsum[1 * HID + tile * 32 + hidl];
        float gg = gsm[b * 132 + 64 + hidl] + g_bsum[2 * HID + tile * 32 + hidl];
        float go = gsm[b * 132 + 96 + hidl] + g_bsum[3 * HID + tile * 32 + hidl];
        int hid  = tile * 32 + hidl;
        int gidx = b * HID + hid;
        float c_new = sigm(gf) * g_c[gidx] + sigm(gi) * tanhf(gg);
        g_c[gidx] = c_new;
        float h = sigm(go) * tanhf(c_new);
        int ks = (tile & 1) * 4 + ksl;
        xn[kc_out * 4096 + ks * 512 + mt * 128 + lane_w * 4 + r] = f2tf32(h);
        if (t == __ldg(&seq_len[b]) - 1) out[gidx] = c_new;
    }
}

// ---------------- launch ----------------
extern "C" void kernel_launch(void* const* d_in, const int* in_sizes, int n_in,
                              void* d_out, int out_size) {
    const int*   tokens    = (const int*)d_in[0];
    const int*   seq_len   = (const int*)d_in[1];
    const float* emb_table = (const float*)d_in[2];
    const float* w_ih      = (const float*)d_in[3];
    const float* w_hh      = (const float*)d_in[4];
    const float* b_ih      = (const float*)d_in[5];
    const float* b_hh      = (const float*)d_in[6];
    float* out = (float*)d_out;

    cudaFuncSetAttribute(step_kernel, cudaFuncAttributeMaxDynamicSharedMemorySize, SMEM_DYN);

    pack_kernel<<<TILES * CHUNKS, 256>>>(w_ih, w_hh);
    init_kernel<<<(T_STEPS * 4096 + 255) / 256, 256>>>(tokens, emb_table, b_ih, b_hh);

    for (int t = 0; t < T_STEPS; ++t) {
        step_kernel<<<TILES, 128, SMEM_DYN>>>(t, seq_len, out);
    }
}

// round 5
// speedup vs baseline: 1.4903x; 1.4903x over previous
#include <cuda_runtime.h>
#include <cuda_fp16.h>
#include <cstdint>

// ---------------- problem constants ----------------
#define T_STEPS 256
#define BATCH   64
#define HID     4096
#define G4      16384
#define NINP    64
#define KC      64            // K elements per chunk
#define CHUNKS  65            // 64 hidden chunks + 1 input chunk
#define TILES   128           // CTAs; 32 hidden units per CTA
#define NSTAGE  7
#define A_U32   2048          // x chunk: 64 b x 64 k fp16 A-fragments = 8KB
#define B_U32   4096          // W chunk: 64 k x 128 rows fp16 B-fragments = 16KB
#define A_BYTES 8192
#define B_BYTES 16384
#define STAGE_BYTES (A_BYTES + B_BYTES)
#define GSM_BYTES (64 * 132 * 4)
#define SMEM_DYN (NSTAGE*STAGE_BYTES + GSM_BYTES + 1024)

// ---------------- device scratch ----------------
__device__ uint32_t g_wpack[(size_t)TILES * CHUNKS * B_U32];  // 136MB fp16 B-fragments
__device__ float    g_bsum[G4];
__device__ uint32_t g_embpack[(size_t)T_STEPS * A_U32];       // fp16 A-fragments per t
__device__ uint32_t g_xpack[2][KC * A_U32];                   // h double buffer
__device__ float    g_c[BATCH * HID];

// ---------------- helpers ----------------
#define DI __device__ __forceinline__

DI uint32_t smem_u32(const void* p) {
    uint32_t a;
    asm("{ .reg .u64 t; cvta.to.shared.u64 t, %1; cvt.u32.u64 %0, t; }" : "=r"(a) : "l"(p));
    return a;
}
DI void cpasync16(uint32_t dst, const void* src) {
    asm volatile("cp.async.cg.shared.global [%0], [%1], 16;" :: "r"(dst), "l"(src) : "memory");
}
DI void cp_commit() { asm volatile("cp.async.commit_group;" ::: "memory"); }
template <int N> DI void cp_wait() { asm volatile("cp.async.wait_group %0;" :: "n"(N) : "memory"); }

// m16n8k16 fp16 MMA, fp32 accum
DI void mma_f16(float* d, const uint32_t* a, const uint32_t* b) {
    asm volatile(
        "mma.sync.aligned.m16n8k16.row.col.f32.f16.f16.f32 "
        "{%0,%1,%2,%3}, {%4,%5,%6,%7}, {%8,%9}, {%0,%1,%2,%3};"
        : "+f"(d[0]), "+f"(d[1]), "+f"(d[2]), "+f"(d[3])
        : "r"(a[0]), "r"(a[1]), "r"(a[2]), "r"(a[3]), "r"(b[0]), "r"(b[1]));
}
DI float sigm(float x) { return 1.0f / (1.0f + __expf(-x)); }
DI uint32_t pack_h2(float lo, float hi) {
    return (uint32_t)__half_as_ushort(__float2half_rn(lo)) |
           ((uint32_t)__half_as_ushort(__float2half_rn(hi)) << 16);
}

// ---------------- pack kernel ----------------
// B-fragment (m16n8k16) per (tile,kc): 4096 u32 = [w(4)][ks(4)][nt(4)][lane(32)][reg(2)]
// k = ks*16 + (lane&3)*2 + reg*8 + {0,1};  row n: gate g=w, hid = tile*32 + nt*8 + (lane>>2)
__global__ void pack_kernel(const float* __restrict__ w_ih, const float* __restrict__ w_hh) {
    int blk  = blockIdx.x;             // tile*CHUNKS + kc
    int tile = blk / CHUNKS;
    int kc   = blk % CHUNKS;
    uint32_t* dst = g_wpack + (size_t)blk * B_U32;
    #pragma unroll
    for (int j = 0; j < 16; j++) {
        int v    = threadIdx.x + j * 256;
        int reg  = v & 1;
        int lane = (v >> 1) & 31;
        int nt   = (v >> 6) & 3;
        int ks   = (v >> 8) & 3;
        int w    = v >> 10;
        int k    = ks * 16 + (lane & 3) * 2 + reg * 8;
        int hid  = tile * 32 + nt * 8 + (lane >> 2);
        size_t srow = (size_t)w * HID + hid;
        float2 val;
        if (kc < 64) val = *(const float2*)&w_hh[srow * HID + (size_t)kc * KC + k];
        else         val = *(const float2*)&w_ih[srow * NINP + k];
        dst[v] = pack_h2(val.x, val.y);
    }
}

// ---------------- init: bias sum, emb A-fragment pack, zero x0/c0 ----------------
// A-fragment per chunk: 2048 u32 = [ks(4)][mt(4)][lane(32)][reg(4)]
// b = mt*16 + (lane>>2) + (reg&1)*8 ; k = ks*16 + (lane&3)*2 + (reg>>1)*8 + {0,1}
__global__ void init_kernel(const int* __restrict__ tokens,
                            const float* __restrict__ emb_table,
                            const float* __restrict__ b_ih,
                            const float* __restrict__ b_hh) {
    int i = blockIdx.x * blockDim.x + threadIdx.x;
    if (i < T_STEPS * A_U32) {
        int t = i >> 11;
        int v = i & 2047;
        int reg = v & 3, lane = (v >> 2) & 31, mt = (v >> 7) & 3, ks = v >> 9;
        int b = mt * 16 + (lane >> 2) + (reg & 1) * 8;
        int k = ks * 16 + (lane & 3) * 2 + (reg >> 1) * 8;
        int tok = tokens[t * BATCH + b];
        float2 e = *(const float2*)&emb_table[tok * NINP + k];
        g_embpack[i] = pack_h2(e.x, e.y);
    }
    if (i < KC * A_U32)     g_xpack[0][i] = 0u;
    if (i < BATCH * HID)    g_c[i] = 0.0f;
    if (i < G4)             g_bsum[i] = b_ih[i] + b_hh[i];
}

// ---------------- one recurrent step ----------------
// 128 CTAs x 256 threads (8 warps). D^T[batch 64][gate rows 128] = x * W.
// Warp w: gate = w>>1, 16-row half = w&1. fp16 m16n8k16, fp32 accum.
__global__ void __launch_bounds__(256, 1)
step_kernel(int t, const int* __restrict__ seq_len, float* __restrict__ out) {
    extern __shared__ char smem_raw[];
    const int tid  = threadIdx.x;
    const int warp = tid >> 5;
    const int lane = tid & 31;
    const int tile = blockIdx.x;
    const int wg   = warp >> 1;          // gate / wpack w index
    const int nsel = warp & 1;           // which 16-row half

    uint32_t sb_raw = smem_u32(smem_raw);
    uint32_t sb = (sb_raw + 1023u) & ~1023u;
    char* smem_al = smem_raw + (sb - sb_raw);

    const uint32_t* wB   = g_wpack + (size_t)tile * (CHUNKS * B_U32);
    const uint32_t* xcur = g_xpack[t & 1];
    const uint32_t* embt = g_embpack + (size_t)t * A_U32;

    auto load_stage = [&](int kc, int s) {
        uint32_t ab = sb + (uint32_t)s * STAGE_BYTES;
        const char* asrc = (kc < 64) ? (const char*)(xcur + (size_t)kc * A_U32)
                                     : (const char*)embt;
        #pragma unroll
        for (int i = 0; i < 2; i++) {                 // A: 8KB linear
            int u = i * 256 + tid;
            cpasync16(ab + (uint32_t)u * 16, asrc + (size_t)u * 16);
        }
        uint32_t bb = ab + A_BYTES;
        const char* bsrc = (const char*)(wB + (size_t)kc * B_U32);
        #pragma unroll
        for (int i = 0; i < 4; i++) {                 // B: 16KB linear
            int u = i * 256 + tid;
            cpasync16(bb + (uint32_t)u * 16, bsrc + (size_t)u * 16);
        }
    };

    #pragma unroll
    for (int s = 0; s < NSTAGE - 1; s++) { load_stage(s, s); cp_commit(); }

    float acc[4][2][4];                               // [mt][j][c]
    #pragma unroll
    for (int mt = 0; mt < 4; mt++)
        #pragma unroll
        for (int j = 0; j < 2; j++)
            #pragma unroll
            for (int c = 0; c < 4; c++) acc[mt][j][c] = 0.0f;

    for (int k = 0; k < CHUNKS; ++k) {
        cp_wait<NSTAGE - 2>();
        __syncthreads();
        if (k + NSTAGE - 1 < CHUNKS) load_stage(k + NSTAGE - 1, (k + NSTAGE - 1) % NSTAGE);
        cp_commit();

        int s = k % NSTAGE;
        const char* sA = smem_al + (size_t)s * STAGE_BYTES;
        const char* sB = sA + A_BYTES;

        #pragma unroll
        for (int ks = 0; ks < 4; ks++) {
            uint32_t af[4][4];
            #pragma unroll
            for (int mt = 0; mt < 4; mt++) {
                uint4 vv = *(const uint4*)(sA + ks * 2048 + mt * 512 + lane * 16);
                af[mt][0] = vv.x; af[mt][1] = vv.y; af[mt][2] = vv.z; af[mt][3] = vv.w;
            }
            uint32_t bf[2][2];
            #pragma unroll
            for (int j = 0; j < 2; j++) {
                int ntIdx = nsel * 2 + j;
                uint2 vv = *(const uint2*)(sB + ((wg * 4 + ks) * 4 + ntIdx) * 256 + lane * 8);
                bf[j][0] = vv.x; bf[j][1] = vv.y;
            }
            #pragma unroll
            for (int mt = 0; mt < 4; mt++)
                #pragma unroll
                for (int j = 0; j < 2; j++)
                    mma_f16(acc[mt][j], af[mt], bf[j]);
        }
    }

    cp_wait<0>();

    // ---- epilogue: C fragments -> gsm [batch 64][gate rows 128] (stride 132) ----
    float* gsm = (float*)(smem_al + NSTAGE * STAGE_BYTES);
    const int warpNbase = wg * 32 + nsel * 16;
    #pragma unroll
    for (int mt = 0; mt < 4; mt++)
        #pragma unroll
        for (int j = 0; j < 2; j++) {
            int b0 = mt * 16 + (lane >> 2);
            int n  = warpNbase + j * 8 + 2 * (lane & 3);
            *(float2*)&gsm[b0 * 132 + n]       = make_float2(acc[mt][j][0], acc[mt][j][1]);
            *(float2*)&gsm[(b0 + 8) * 132 + n] = make_float2(acc[mt][j][2], acc[mt][j][3]);
        }
    __syncthreads();

    // LSTM update; write h as fp16 pairs directly in A-fragment order.
    const int hidbase = tile * 32;
    uint32_t* xn = g_xpack[(t + 1) & 1];
    #pragma unroll
    for (int i = 0; i < 4; i++) {
        int u  = i * 256 + tid;              // 1024 units: (b, hid pair)
        int hp = u & 15;
        int b  = u >> 4;
        int h0 = hp * 2, h1 = hp * 2 + 1;
        float gi0 = gsm[b * 132 +   0 + h0] + g_bsum[0 * HID + hidbase + h0];
        float gf0 = gsm[b * 132 +  32 + h0] + g_bsum[1 * HID + hidbase + h0];
        float gg0 = gsm[b * 132 +  64 + h0] + g_bsum[2 * HID + hidbase + h0];
        float go0 = gsm[b * 132 +  96 + h0] + g_bsum[3 * HID + hidbase + h0];
        float gi1 = gsm[b * 132 +   0 + h1] + g_bsum[0 * HID + hidbase + h1];
        float gf1 = gsm[b * 132 +  32 + h1] + g_bsum[1 * HID + hidbase + h1];
        float gg1 = gsm[b * 132 +  64 + h1] + g_bsum[2 * HID + hidbase + h1];
        float go1 = gsm[b * 132 +  96 + h1] + g_bsum[3 * HID + hidbase + h1];
        int idx0 = b * HID + hidbase + h0;
        int idx1 = idx0 + 1;
        float c0 = sigm(gf0) * g_c[idx0] + sigm(gi0) * tanhf(gg0);
        float c1 = sigm(gf1) * g_c[idx1] + sigm(gi1) * tanhf(gg1);
        g_c[idx0] = c0; g_c[idx1] = c1;
        float hh0 = sigm(go0) * tanhf(c0);
        float hh1 = sigm(go1) * tanhf(c1);
        int mt   = b >> 4;
        int ln   = ((b & 7) << 2) | (hp & 3);
        int reg  = (((hp >> 2) & 1) << 1) | ((b >> 3) & 1);
        int ks   = (tile & 1) * 2 + (hp >> 3);
        xn[(tile >> 1) * A_U32 + ks * 512 + mt * 128 + ln * 4 + reg] = pack_h2(hh0, hh1);
        if (t == __ldg(&seq_len[b]) - 1) { out[idx0] = c0; out[idx1] = c1; }
    }
}

// ---------------- launch ----------------
extern "C" void kernel_launch(void* const* d_in, const int* in_sizes, int n_in,
                              void* d_out, int out_size) {
    const int*   tokens    = (const int*)d_in[0];
    const int*   seq_len   = (const int*)d_in[1];
    const float* emb_table = (const float*)d_in[2];
    const float* w_ih      = (const float*)d_in[3];
    const float* w_hh      = (const float*)d_in[4];
    const float* b_ih      = (const float*)d_in[5];
    const float* b_hh      = (const float*)d_in[6];
    float* out = (float*)d_out;

    cudaFuncSetAttribute(step_kernel, cudaFuncAttributeMaxDynamicSharedMemorySize, SMEM_DYN);

    pack_kernel<<<TILES * CHUNKS, 256>>>(w_ih, w_hh);
    init_kernel<<<(T_STEPS * A_U32 + 255) / 256, 256>>>(tokens, emb_table, b_ih, b_hh);

    for (int t = 0; t < T_STEPS; ++t) {
        step_kernel<<<TILES, 256, SMEM_DYN>>>(t, seq_len, out);
    }
}

// round 6
// speedup vs baseline: 2.0043x; 1.3450x over previous
#include <cuda_runtime.h>
#include <cuda_fp16.h>
#include <cstdint>

// ---------------- problem constants ----------------
#define T_STEPS 256
#define BATCH   64
#define HID     4096
#define G4      16384
#define NINP    64
#define KC      64            // K elements per chunk
#define CHUNKS  65            // 64 hidden chunks + 1 input chunk
#define TILES   256           // CTAs; 16 hidden units per CTA
#define NSTAGE  6
#define A_U32   2048          // x chunk: 64 b x 64 k fp16 A-fragments = 8KB
#define B_U32   2048          // W chunk per tile: 64 rows x 64 k fp16 B-fragments = 8KB
#define A_BYTES 8192
#define B_BYTES 8192
#define STAGE_BYTES (A_BYTES + B_BYTES)
#define SMEM_DYN (NSTAGE*STAGE_BYTES)   // 96KB -> 2 CTAs/SM

// ---------------- device scratch ----------------
__device__ uint32_t g_wpack[(size_t)TILES * CHUNKS * B_U32];  // 136MB fp16 B-fragments
__device__ float    g_bsum[G4];
__device__ uint32_t g_embpack[(size_t)T_STEPS * A_U32];       // fp16 A-fragments per t
__device__ uint32_t g_xpack[2][KC * A_U32];                   // h double buffer
__device__ float    g_c[BATCH * HID];

// ---------------- helpers ----------------
#define DI __device__ __forceinline__

DI uint32_t smem_u32(const void* p) {
    uint32_t a;
    asm("{ .reg .u64 t; cvta.to.shared.u64 t, %1; cvt.u32.u64 %0, t; }" : "=r"(a) : "l"(p));
    return a;
}
DI void cpasync16(uint32_t dst, const void* src) {
    asm volatile("cp.async.cg.shared.global [%0], [%1], 16;" :: "r"(dst), "l"(src) : "memory");
}
DI void cp_commit() { asm volatile("cp.async.commit_group;" ::: "memory"); }
template <int N> DI void cp_wait() { asm volatile("cp.async.wait_group %0;" :: "n"(N) : "memory"); }

// m16n8k16 fp16 MMA, fp32 accum
DI void mma_f16(float* d, const uint32_t* a, const uint32_t* b) {
    asm volatile(
        "mma.sync.aligned.m16n8k16.row.col.f32.f16.f16.f32 "
        "{%0,%1,%2,%3}, {%4,%5,%6,%7}, {%8,%9}, {%0,%1,%2,%3};"
        : "+f"(d[0]), "+f"(d[1]), "+f"(d[2]), "+f"(d[3])
        : "r"(a[0]), "r"(a[1]), "r"(a[2]), "r"(a[3]), "r"(b[0]), "r"(b[1]));
}
DI float sigm(float x) { return 1.0f / (1.0f + __expf(-x)); }
DI uint32_t pack_h2(float lo, float hi) {
    return (uint32_t)__half_as_ushort(__float2half_rn(lo)) |
           ((uint32_t)__half_as_ushort(__float2half_rn(hi)) << 16);
}

// ---------------- pack kernel ----------------
// B-fragment (m16n8k16) per (tile,kc): 2048 u32 = [ks(4)][wr(2)][nt(4)][lane(32)][reg(2)]
// k = ks*16 + (lane&3)*2 + reg*8 + {0,1}
// row n = wr*32 + nt*8 + (lane>>2); gate g = n>>4; hid = tile*16 + (n&15)
__global__ void pack_kernel(const float* __restrict__ w_ih, const float* __restrict__ w_hh) {
    int blk  = blockIdx.x;             // tile*CHUNKS + kc
    int tile = blk / CHUNKS;
    int kc   = blk % CHUNKS;
    uint32_t* dst = g_wpack + (size_t)blk * B_U32;
    #pragma unroll
    for (int j = 0; j < 8; j++) {
        int v    = threadIdx.x + j * 256;
        int reg  = v & 1;
        int lane = (v >> 1) & 31;
        int nt   = (v >> 6) & 3;
        int wr   = (v >> 8) & 1;
        int ks   = v >> 9;
        int k    = ks * 16 + (lane & 3) * 2 + reg * 8;
        int n    = wr * 32 + nt * 8 + (lane >> 2);
        int g    = n >> 4;
        int hid  = tile * 16 + (n & 15);
        size_t srow = (size_t)g * HID + hid;
        float2 val;
        if (kc < 64) val = *(const float2*)&w_hh[srow * HID + (size_t)kc * KC + k];
        else         val = *(const float2*)&w_ih[srow * NINP + k];
        dst[v] = pack_h2(val.x, val.y);
    }
}

// ---------------- init: bias sum, emb A-fragment pack, zero x0/c0 ----------------
// A-fragment per chunk: 2048 u32 = [ks(4)][mt(4)][lane(32)][reg(4)]
// b = mt*16 + (lane>>2) + (reg&1)*8 ; k = ks*16 + (lane&3)*2 + (reg>>1)*8 + {0,1}
__global__ void init_kernel(const int* __restrict__ tokens,
                            const float* __restrict__ emb_table,
                            const float* __restrict__ b_ih,
                            const float* __restrict__ b_hh) {
    int i = blockIdx.x * blockDim.x + threadIdx.x;
    if (i < T_STEPS * A_U32) {
        int t = i >> 11;
        int v = i & 2047;
        int reg = v & 3, lane = (v >> 2) & 31, mt = (v >> 7) & 3, ks = v >> 9;
        int b = mt * 16 + (lane >> 2) + (reg & 1) * 8;
        int k = ks * 16 + (lane & 3) * 2 + (reg >> 1) * 8;
        int tok = tokens[t * BATCH + b];
        float2 e = *(const float2*)&emb_table[tok * NINP + k];
        g_embpack[i] = pack_h2(e.x, e.y);
    }
    if (i < KC * A_U32)     g_xpack[0][i] = 0u;
    if (i < BATCH * HID)    g_c[i] = 0.0f;
    if (i < G4)             g_bsum[i] = b_ih[i] + b_hh[i];
}

// ---------------- one recurrent step ----------------
// 256 CTAs x 128 threads (4 warps), 2 CTAs/SM. CTA: 16 hidden units, M=64 gate rows.
// D^T[batch 64][rows 64] = x * W. Warp: wr=warp&1 row half, wb=warp>>1 batch half.
__global__ void __launch_bounds__(128, 2)
step_kernel(int t, const int* __restrict__ seq_len, float* __restrict__ out) {
    extern __shared__ char smem_al[];
    const int tid  = threadIdx.x;
    const int warp = tid >> 5;
    const int lane = tid & 31;
    const int tile = blockIdx.x;
    const int wr   = warp & 1;           // row half (32 rows)
    const int wb   = warp >> 1;          // batch half (32 batch)

    uint32_t sb = smem_u32(smem_al);

    const uint32_t* wB   = g_wpack + (size_t)tile * (CHUNKS * B_U32);
    const uint32_t* xcur = g_xpack[t & 1];
    const uint32_t* embt = g_embpack + (size_t)t * A_U32;

    auto load_stage = [&](int kc, int s) {
        uint32_t ab = sb + (uint32_t)s * STAGE_BYTES;
        const char* asrc = (kc < 64) ? (const char*)(xcur + (size_t)kc * A_U32)
                                     : (const char*)embt;
        #pragma unroll
        for (int i = 0; i < 4; i++) {                 // A: 8KB linear
            int u = i * 128 + tid;
            cpasync16(ab + (uint32_t)u * 16, asrc + (size_t)u * 16);
        }
        uint32_t bb = ab + A_BYTES;
        const char* bsrc = (const char*)(wB + (size_t)kc * B_U32);
        #pragma unroll
        for (int i = 0; i < 4; i++) {                 // B: 8KB linear
            int u = i * 128 + tid;
            cpasync16(bb + (uint32_t)u * 16, bsrc + (size_t)u * 16);
        }
    };

    #pragma unroll
    for (int s = 0; s < NSTAGE - 1; s++) { load_stage(s, s); cp_commit(); }

    float acc[2][4][4];                               // [mt][nt][c]
    #pragma unroll
    for (int mt = 0; mt < 2; mt++)
        #pragma unroll
        for (int nt = 0; nt < 4; nt++)
            #pragma unroll
            for (int c = 0; c < 4; c++) acc[mt][nt][c] = 0.0f;

    for (int k = 0; k < CHUNKS; ++k) {
        cp_wait<NSTAGE - 2>();
        __syncthreads();
        if (k + NSTAGE - 1 < CHUNKS) load_stage(k + NSTAGE - 1, (k + NSTAGE - 1) % NSTAGE);
        cp_commit();

        int s = k % NSTAGE;
        const char* sA = smem_al + (size_t)s * STAGE_BYTES;
        const char* sB = sA + A_BYTES;

        #pragma unroll
        for (int ks = 0; ks < 4; ks++) {
            uint32_t af[2][4];
            #pragma unroll
            for (int mt = 0; mt < 2; mt++) {
                uint4 vv = *(const uint4*)(sA + ks * 2048 + (wb * 2 + mt) * 512 + lane * 16);
                af[mt][0] = vv.x; af[mt][1] = vv.y; af[mt][2] = vv.z; af[mt][3] = vv.w;
            }
            uint32_t bf[4][2];
            #pragma unroll
            for (int nt = 0; nt < 4; nt++) {
                uint2 vv = *(const uint2*)(sB + (((ks * 2 + wr) * 4 + nt) * 32 + lane) * 8);
                bf[nt][0] = vv.x; bf[nt][1] = vv.y;
            }
            #pragma unroll
            for (int mt = 0; mt < 2; mt++)
                #pragma unroll
                for (int nt = 0; nt < 4; nt++)
                    mma_f16(acc[mt][nt], af[mt], bf[nt]);
        }
    }

    cp_wait<0>();
    __syncthreads();                                  // stages dead; gsm aliases them

    // ---- epilogue: C fragments -> gsm [batch 64][rows 64] stride 68 ----
    float* gsm = (float*)smem_al;
    #pragma unroll
    for (int mt = 0; mt < 2; mt++)
        #pragma unroll
        for (int nt = 0; nt < 4; nt++) {
            int b0 = (wb * 2 + mt) * 16 + (lane >> 2);
            int n  = wr * 32 + nt * 8 + 2 * (lane & 3);
            *(float2*)&gsm[b0 * 68 + n]       = make_float2(acc[mt][nt][0], acc[mt][nt][1]);
            *(float2*)&gsm[(b0 + 8) * 68 + n] = make_float2(acc[mt][nt][2], acc[mt][nt][3]);
        }
    __syncthreads();

    // LSTM update; write h as fp16 pairs directly in A-fragment order.
    const int hidbase = tile * 16;
    uint32_t* xn = g_xpack[(t + 1) & 1];
    #pragma unroll
    for (int i = 0; i < 4; i++) {
        int u  = i * 128 + tid;              // 512 units: (b, hid pair hp)
        int hp = u & 7;
        int b  = u >> 3;
        int h0 = hp * 2, h1 = hp * 2 + 1;
        float gi0 = gsm[b * 68 +  0 + h0] + g_bsum[0 * HID + hidbase + h0];
        float gf0 = gsm[b * 68 + 16 + h0] + g_bsum[1 * HID + hidbase + h0];
        float gg0 = gsm[b * 68 + 32 + h0] + g_bsum[2 * HID + hidbase + h0];
        float go0 = gsm[b * 68 + 48 + h0] + g_bsum[3 * HID + hidbase + h0];
        float gi1 = gsm[b * 68 +  0 + h1] + g_bsum[0 * HID + hidbase + h1];
        float gf1 = gsm[b * 68 + 16 + h1] + g_bsum[1 * HID + hidbase + h1];
        float gg1 = gsm[b * 68 + 32 + h1] + g_bsum[2 * HID + hidbase + h1];
        float go1 = gsm[b * 68 + 48 + h1] + g_bsum[3 * HID + hidbase + h1];
        int idx0 = b * HID + hidbase + h0;
        int idx1 = idx0 + 1;
        float c0 = sigm(gf0) * g_c[idx0] + sigm(gi0) * tanhf(gg0);
        float c1 = sigm(gf1) * g_c[idx1] + sigm(gi1) * tanhf(gg1);
        g_c[idx0] = c0; g_c[idx1] = c1;
        float hh0 = sigm(go0) * tanhf(c0);
        float hh1 = sigm(go1) * tanhf(c1);
        // A-fragment address: ks=tile&3; lane=(b&7)*4+(hp&3); reg=(hp>>2)*2+((b>>3)&1); mt=b>>4
        int ksx  = tile & 3;
        int lnx  = ((b & 7) << 2) | (hp & 3);
        int regx = ((hp >> 2) << 1) | ((b >> 3) & 1);
        int mtx  = b >> 4;
        xn[(tile >> 2) * A_U32 + ((ksx * 4 + mtx) * 32 + lnx) * 4 + regx] = pack_h2(hh0, hh1);
        if (t == __ldg(&seq_len[b]) - 1) { out[idx0] = c0; out[idx1] = c1; }
    }
}

// ---------------- launch ----------------
extern "C" void kernel_launch(void* const* d_in, const int* in_sizes, int n_in,
                              void* d_out, int out_size) {
    const int*   tokens    = (const int*)d_in[0];
    const int*   seq_len   = (const int*)d_in[1];
    const float* emb_table = (const float*)d_in[2];
    const float* w_ih      = (const float*)d_in[3];
    const float* w_hh      = (const float*)d_in[4];
    const float* b_ih      = (const float*)d_in[5];
    const float* b_hh      = (const float*)d_in[6];
    float* out = (float*)d_out;

    cudaFuncSetAttribute(step_kernel, cudaFuncAttributeMaxDynamicSharedMemorySize, SMEM_DYN);

    pack_kernel<<<TILES * CHUNKS, 256>>>(w_ih, w_hh);
    init_kernel<<<(T_STEPS * A_U32 + 255) / 256, 256>>>(tokens, emb_table, b_ih, b_hh);

    for (int t = 0; t < T_STEPS; ++t) {
        step_kernel<<<TILES, 128, SMEM_DYN>>>(t, seq_len, out);
    }
}